// round 1
// baseline (speedup 1.0000x reference)
#include <cuda_runtime.h>
#include <math.h>

#define KS 14      // source subjects (S-1)
#define BSZ 1024   // batch per subject
#define CD 2048    // input channels
#define DD 512     // hidden dim
#define M2 2048    // rows of "total" per k  (outs ++ t_outs)

// ---------------- scratch (static device globals: allowed) ----------------
__device__ float  g_Wt[(size_t)KS * CD * DD];      // W_add[idx_k] transposed -> (k, c, d)
__device__ float  g_total[(size_t)KS * M2 * DD];   // [outs_k ; t_outs_k]  (k, i, d)
__device__ float  g_totalT[(size_t)KS * DD * M2];  // transpose            (k, d, i)
__device__ float  g_sq[KS * M2];                   // row squared norms
__device__ float  g_cs[16 * KS * DD];              // column-sum partials
__device__ float  g_inv16[KS];                     // 1/(16 * base_bandwidth)
__device__ double g_mmd[KS];                       // signed kernel sums
__device__ float  g_tprob[BSZ * 3];                // accumulated target softmax
__device__ double g_cls;
__device__ double g_disc;
__device__ int    g_pred;

// ---------------- zero accumulators (must run every launch: graph replay) -----
__global__ void k_zero() {
    int t = blockIdx.x * blockDim.x + threadIdx.x;
    if (t < BSZ * 3) g_tprob[t] = 0.f;
    if (t < KS)      g_mmd[t] = 0.0;
    if (t == 0) { g_cls = 0.0; g_disc = 0.0; g_pred = 0; }
}

// ---------------- transpose W_add[idx_k] (512x2048) -> g_Wt (2048x512) -------
__global__ void k_transW(const float* __restrict__ W_add, const int* __restrict__ subj_p) {
    __shared__ float tile[32][33];
    int k = blockIdx.z;
    int subj = *subj_p;
    int sk = (k < subj) ? k : k + 1;
    int d0 = blockIdx.y * 32, c0 = blockIdx.x * 32;
    const float* Win = W_add + (size_t)sk * DD * CD;
    float* Wout = g_Wt + (size_t)k * CD * DD;
    int tx = threadIdx.x, ty = threadIdx.y;
    #pragma unroll
    for (int r = ty; r < 32; r += 8)
        tile[r][tx] = Win[(size_t)(d0 + r) * CD + c0 + tx];
    __syncthreads();
    #pragma unroll
    for (int r = ty; r < 32; r += 8)
        Wout[(size_t)(c0 + r) * DD + d0 + tx] = tile[tx][r];
}

// ---------------- stage-1 SGEMM: total[k] = A_k (2048x2048) @ Wt_k (2048x512) ---
__global__ __launch_bounds__(256) void k_sgemm1(
    const float* __restrict__ x, const float* __restrict__ b_add,
    const int* __restrict__ subj_p) {
    int k = blockIdx.z;
    int subj = *subj_p;
    int sk = (k < subj) ? k : k + 1;
    int i0 = blockIdx.y * 128;
    int n0 = blockIdx.x * 128;
    // rows 0..1023 of A_k are src subject sk; rows 1024..2047 are target subject
    int arowbase = (i0 < BSZ) ? (sk * BSZ + i0) : (subj * BSZ + (i0 - BSZ));
    const float* A  = x + (size_t)arowbase * CD;
    const float* Bm = g_Wt + (size_t)k * CD * DD + n0;
    float* Cm = g_total + (size_t)k * M2 * DD + (size_t)i0 * DD + n0;

    __shared__ float As[8][128];
    __shared__ float Bs[8][128];
    int tid = threadIdx.x;
    int tx = tid & 15, ty = tid >> 4;
    int arow = tid >> 1;
    int acol = (tid & 1) * 4;
    int brow = tid >> 5;
    int bcol = (tid & 31) * 4;

    float acc[8][8];
    #pragma unroll
    for (int r = 0; r < 8; r++)
        #pragma unroll
        for (int c = 0; c < 8; c++) acc[r][c] = 0.f;

    for (int kt = 0; kt < CD; kt += 8) {
        float4 av = *(const float4*)(A + (size_t)arow * CD + kt + acol);
        As[acol + 0][arow] = av.x;
        As[acol + 1][arow] = av.y;
        As[acol + 2][arow] = av.z;
        As[acol + 3][arow] = av.w;
        *(float4*)&Bs[brow][bcol] = *(const float4*)(Bm + (size_t)(kt + brow) * DD + bcol);
        __syncthreads();
        #pragma unroll
        for (int kk = 0; kk < 8; kk++) {
            float a[8], b[8];
            *(float4*)&a[0] = *(const float4*)&As[kk][ty * 8];
            *(float4*)&a[4] = *(const float4*)&As[kk][ty * 8 + 4];
            *(float4*)&b[0] = *(const float4*)&Bs[kk][tx * 8];
            *(float4*)&b[4] = *(const float4*)&Bs[kk][tx * 8 + 4];
            #pragma unroll
            for (int r = 0; r < 8; r++)
                #pragma unroll
                for (int c = 0; c < 8; c++) acc[r][c] += a[r] * b[c];
        }
        __syncthreads();
    }
    float bias[8];
    #pragma unroll
    for (int c = 0; c < 8; c++) bias[c] = b_add[sk * DD + n0 + tx * 8 + c];
    #pragma unroll
    for (int r = 0; r < 8; r++) {
        #pragma unroll
        for (int c = 0; c < 8; c++) acc[r][c] += bias[c];
        float* dst = Cm + (size_t)(ty * 8 + r) * DD + tx * 8;
        *(float4*)dst = *(float4*)&acc[r][0];
        *(float4*)(dst + 4) = *(float4*)&acc[r][4];
    }
}

// ---------------- transpose total -> totalT ---------------------------------
__global__ void k_transT() {
    __shared__ float tile[32][33];
    int k = blockIdx.z;
    int i0 = blockIdx.y * 32, d0 = blockIdx.x * 32;
    const float* Tin = g_total + (size_t)k * M2 * DD;
    float* Tout = g_totalT + (size_t)k * DD * M2;
    int tx = threadIdx.x, ty = threadIdx.y;
    #pragma unroll
    for (int r = ty; r < 32; r += 8)
        tile[r][tx] = Tin[(size_t)(i0 + r) * DD + d0 + tx];
    __syncthreads();
    #pragma unroll
    for (int r = ty; r < 32; r += 8)
        Tout[(size_t)(d0 + r) * M2 + i0 + tx] = tile[tx][r];
}

// ---------------- row squared norms ------------------------------------------
__global__ void k_sq() {
    int gw = (blockIdx.x * blockDim.x + threadIdx.x) >> 5;
    int lane = threadIdx.x & 31;
    if (gw >= KS * M2) return;
    const float* row = g_total + (size_t)gw * DD;
    float s = 0.f;
    for (int d = lane; d < DD; d += 32) { float v = row[d]; s += v * v; }
    #pragma unroll
    for (int o = 16; o; o >>= 1) s += __shfl_xor_sync(0xffffffffu, s, o);
    if (lane == 0) g_sq[gw] = s;
}

// ---------------- column-sum partials (for sum(Gram) = ||colsum||^2) ---------
__global__ void k_colsum() {
    int k = blockIdx.x, part = blockIdx.y;
    int d = threadIdx.x;
    const float* T = g_total + (size_t)k * M2 * DD;
    float s = 0.f;
    int ib = part * 128;
    for (int i = ib; i < ib + 128; i++) s += T[(size_t)i * DD + d];
    g_cs[(part * KS + k) * DD + d] = s;
}

// ---------------- bandwidth: sum(d2) = 2m*sum(sq) - 2*||colsum||^2 ------------
__global__ void k_bw() {
    __shared__ float red[512];
    int k = blockIdx.x, d = threadIdx.x;
    float s = 0.f;
    for (int p = 0; p < 16; p++) s += g_cs[(p * KS + k) * DD + d];
    red[d] = s * s;
    __syncthreads();
    for (int st = 256; st > 0; st >>= 1) { if (d < st) red[d] += red[d + st]; __syncthreads(); }
    float ssum = red[0];
    __syncthreads();
    float q = 0.f;
    for (int i = d; i < M2; i += 512) q += g_sq[k * M2 + i];
    red[d] = q;
    __syncthreads();
    for (int st = 256; st > 0; st >>= 1) { if (d < st) red[d] += red[d + st]; __syncthreads(); }
    if (d == 0) {
        double sqsum = (double)red[0];
        double m = (double)M2;
        double sumd2 = 2.0 * m * sqsum - 2.0 * (double)ssum;
        double bw = sumd2 / (m * m - m);
        bw = bw / 4.0;                 // / KERNEL_MUL^(KERNEL_NUM//2)
        g_inv16[k] = (float)(1.0 / (16.0 * bw));
    }
}

// ---------------- Gram + fused multi-bandwidth RBF, upper triangle only -------
__global__ __launch_bounds__(256) void k_gram() {
    int k = blockIdx.z;
    int bi = blockIdx.y, bj = blockIdx.x;
    if (bj < bi) return;
    int i0 = bi * 128, j0 = bj * 128;
    const float* A  = g_total  + (size_t)k * M2 * DD + (size_t)i0 * DD;
    const float* Bm = g_totalT + (size_t)k * DD * M2 + j0;

    __shared__ float As[8][128];
    __shared__ float Bs[8][128];
    int tid = threadIdx.x;
    int tx = tid & 15, ty = tid >> 4;
    int arow = tid >> 1;
    int acol = (tid & 1) * 4;
    int brow = tid >> 5;
    int bcol = (tid & 31) * 4;

    float acc[8][8];
    #pragma unroll
    for (int r = 0; r < 8; r++)
        #pragma unroll
        for (int c = 0; c < 8; c++) acc[r][c] = 0.f;

    for (int kt = 0; kt < DD; kt += 8) {
        float4 av = *(const float4*)(A + (size_t)arow * DD + kt + acol);
        As[acol + 0][arow] = av.x;
        As[acol + 1][arow] = av.y;
        As[acol + 2][arow] = av.z;
        As[acol + 3][arow] = av.w;
        *(float4*)&Bs[brow][bcol] = *(const float4*)(Bm + (size_t)(kt + brow) * M2 + bcol);
        __syncthreads();
        #pragma unroll
        for (int kk = 0; kk < 8; kk++) {
            float a[8], b[8];
            *(float4*)&a[0] = *(const float4*)&As[kk][ty * 8];
            *(float4*)&a[4] = *(const float4*)&As[kk][ty * 8 + 4];
            *(float4*)&b[0] = *(const float4*)&Bs[kk][tx * 8];
            *(float4*)&b[4] = *(const float4*)&Bs[kk][tx * 8 + 4];
            #pragma unroll
            for (int r = 0; r < 8; r++)
                #pragma unroll
                for (int c = 0; c < 8; c++) acc[r][c] += a[r] * b[c];
        }
        __syncthreads();
    }

    float inv = g_inv16[k];
    float sqi[8], sqj[8];
    #pragma unroll
    for (int r = 0; r < 8; r++) sqi[r] = g_sq[k * M2 + i0 + ty * 8 + r];
    #pragma unroll
    for (int c = 0; c < 8; c++) sqj[c] = g_sq[k * M2 + j0 + tx * 8 + c];

    float tsum = 0.f;
    #pragma unroll
    for (int r = 0; r < 8; r++) {
        #pragma unroll
        for (int c = 0; c < 8; c++) {
            float d2 = sqi[r] + sqj[c] - 2.f * acc[r][c];
            float e = __expf(-d2 * inv);   // exp(-d2/(16*bw))
            float ss = e;                  // denominators bw*{16,8,4,2,1} via squaring
            e *= e; ss += e;
            e *= e; ss += e;
            e *= e; ss += e;
            e *= e; ss += e;
            tsum += ss;
        }
    }
    #pragma unroll
    for (int o = 16; o; o >>= 1) tsum += __shfl_xor_sync(0xffffffffu, tsum, o);
    __shared__ float wsum[8];
    if ((tid & 31) == 0) wsum[tid >> 5] = tsum;
    __syncthreads();
    if (tid == 0) {
        float bs = 0.f;
        #pragma unroll
        for (int w = 0; w < 8; w++) bs += wsum[w];
        float sgn = ((bi < 8) == (bj < 8)) ? 1.f : -1.f;  // XX/YY:+  XY/YX:-
        float wgt = (bi == bj) ? 1.f : 2.f;               // symmetry
        atomicAdd(&g_mmd[k], (double)(sgn * wgt * bs));
    }
}

// ---------------- classifier head: cls loss + target prob accumulation -------
__global__ void k_cls(const float* __restrict__ y, const float* __restrict__ W_cls,
                      const float* __restrict__ b_cls, const int* __restrict__ subj_p) {
    int gw = (blockIdx.x * blockDim.x + threadIdx.x) >> 5;
    int lane = threadIdx.x & 31;
    if (gw >= KS * M2) return;
    int k = gw / M2;
    int r = gw % M2;
    const float* row = g_total + (size_t)gw * DD;
    const float* Wc = W_cls + (size_t)k * 3 * DD;   // W_cls[:K], NOT idx!
    float a0 = 0.f, a1 = 0.f, a2 = 0.f;
    for (int d = lane; d < DD; d += 32) {
        float v = fmaxf(row[d], 0.f);
        a0 += v * Wc[d];
        a1 += v * Wc[DD + d];
        a2 += v * Wc[2 * DD + d];
    }
    #pragma unroll
    for (int o = 16; o; o >>= 1) {
        a0 += __shfl_xor_sync(0xffffffffu, a0, o);
        a1 += __shfl_xor_sync(0xffffffffu, a1, o);
        a2 += __shfl_xor_sync(0xffffffffu, a2, o);
    }
    if (lane == 0) {
        int subj = *subj_p;
        float l0 = a0 + b_cls[k * 3 + 0];
        float l1 = a1 + b_cls[k * 3 + 1];
        float l2 = a2 + b_cls[k * 3 + 2];
        float m = fmaxf(l0, fmaxf(l1, l2));
        float e0 = expf(l0 - m), e1 = expf(l1 - m), e2 = expf(l2 - m);
        float sum = e0 + e1 + e2;
        if (r < BSZ) {
            int sk = (k < subj) ? k : k + 1;
            const float* yr = y + (size_t)(sk * BSZ + r) * 3;
            int lab = (yr[1] > yr[0]) ? ((yr[2] > yr[1]) ? 2 : 1) : ((yr[2] > yr[0]) ? 2 : 0);
            float li = (lab == 0) ? l0 : ((lab == 1) ? l1 : l2);
            float loss = m + logf(sum) - li;   // logsumexp - logit[label]
            atomicAdd(&g_cls, (double)loss);
        } else {
            int b = r - BSZ;
            float invs = 1.f / sum;
            atomicAdd(&g_tprob[b * 3 + 0], e0 * invs);
            atomicAdd(&g_tprob[b * 3 + 1], e1 * invs);
            atomicAdd(&g_tprob[b * 3 + 2], e2 * invs);
        }
    }
}

// ---------------- prediction count -------------------------------------------
__global__ void k_pred(const float* __restrict__ y, const int* __restrict__ subj_p) {
    int b = blockIdx.x * blockDim.x + threadIdx.x;
    if (b >= BSZ) return;
    int subj = *subj_p;
    float p0 = g_tprob[b * 3], p1 = g_tprob[b * 3 + 1], p2 = g_tprob[b * 3 + 2];
    int am = (p1 > p0) ? ((p2 > p1) ? 2 : 1) : ((p2 > p0) ? 2 : 0);
    const float* yr = y + (size_t)(subj * BSZ + b) * 3;
    int lab = (yr[1] > yr[0]) ? ((yr[2] > yr[1]) ? 2 : 1) : ((yr[2] > yr[0]) ? 2 : 0);
    if (am == lab) atomicAdd(&g_pred, 1);
}

// ---------------- pairwise softmax discrepancy --------------------------------
__global__ void k_disc() {
    __shared__ float P[KS][513];
    int b = blockIdx.x;
    int w = threadIdx.x >> 5, lane = threadIdx.x & 31;
    for (int k = w; k < KS; k += 8) {
        const float* row = g_total + ((size_t)k * M2 + b) * DD;
        float m = -1e30f;
        for (int d = lane; d < DD; d += 32) m = fmaxf(m, row[d]);
        #pragma unroll
        for (int o = 16; o; o >>= 1) m = fmaxf(m, __shfl_xor_sync(0xffffffffu, m, o));
        float ssum = 0.f;
        for (int d = lane; d < DD; d += 32) {
            float e = __expf(row[d] - m);
            P[k][d] = e;
            ssum += e;
        }
        #pragma unroll
        for (int o = 16; o; o >>= 1) ssum += __shfl_xor_sync(0xffffffffu, ssum, o);
        float invs = 1.f / ssum;
        for (int d = lane; d < DD; d += 32) P[k][d] *= invs;
    }
    __syncthreads();
    float acc = 0.f;
    for (int d = threadIdx.x; d < DD; d += 256) {
        float p[KS];
        #pragma unroll
        for (int k = 0; k < KS; k++) p[k] = P[k][d];
        #pragma unroll
        for (int i = 0; i < KS; i++)
            #pragma unroll
            for (int j = i + 1; j < KS; j++)
                acc += fabsf(p[i] - p[j]);
    }
    #pragma unroll
    for (int o = 16; o; o >>= 1) acc += __shfl_xor_sync(0xffffffffu, acc, o);
    __shared__ float ws[8];
    if ((threadIdx.x & 31) == 0) ws[threadIdx.x >> 5] = acc;
    __syncthreads();
    if (threadIdx.x == 0) {
        float s = 0.f;
        #pragma unroll
        for (int i = 0; i < 8; i++) s += ws[i];
        atomicAdd(&g_disc, (double)s);
    }
}

// ---------------- finalize -----------------------------------------------------
__global__ void k_fin(float* __restrict__ out) {
    if (threadIdx.x == 0 && blockIdx.x == 0) {
        double mmd = 0.0;
        for (int k = 0; k < KS; k++) mmd += g_mmd[k];
        mmd /= (double)KS * (double)BSZ * (double)BSZ;
        out[0] = (float)(0.1 * mmd);
        double disc = g_disc / ((double)BSZ * (double)DD) * 2.0 / ((double)KS * (KS - 1));
        out[1] = (float)(0.4 * disc);
        out[2] = (float)(g_cls / ((double)KS * (double)BSZ));
        out[3] = (float)g_pred;
        out[4] = (float)BSZ;
    }
}

// ---------------- launch --------------------------------------------------------
extern "C" void kernel_launch(void* const* d_in, const int* in_sizes, int n_in,
                              void* d_out, int out_size) {
    const float* x     = (const float*)d_in[0];
    const float* y     = (const float*)d_in[1];
    // d_in[2] = subject_label (unused by reference)
    const float* W_add = (const float*)d_in[3];
    const float* b_add = (const float*)d_in[4];
    const float* W_cls = (const float*)d_in[5];
    const float* b_cls = (const float*)d_in[6];
    const int*   subj  = (const int*)d_in[7];

    k_zero<<<12, 256>>>();
    k_transW<<<dim3(64, 16, KS), dim3(32, 8)>>>(W_add, subj);
    k_sgemm1<<<dim3(4, 16, KS), 256>>>(x, b_add, subj);
    k_transT<<<dim3(16, 64, KS), dim3(32, 8)>>>();
    k_sq<<<(KS * M2) / 8, 256>>>();
    k_colsum<<<dim3(KS, 16), 512>>>();
    k_bw<<<KS, 512>>>();
    k_gram<<<dim3(16, 16, KS), 256>>>();
    k_cls<<<(KS * M2) / 8, 256>>>(y, W_cls, b_cls, subj);
    k_pred<<<4, 256>>>(y, subj);
    k_disc<<<BSZ, 256>>>();
    k_fin<<<1, 32>>>((float*)d_out);
}

// round 3
// speedup vs baseline: 2.5671x; 2.5671x over previous
#include <cuda_runtime.h>
#include <cuda_bf16.h>
#include <math.h>
#include <stdint.h>

#define KS 14      // source subjects (S-1)
#define SNUM 15
#define BSZ 1024
#define CD 2048
#define DD 512
#define M2 2048

#define STAGE_B 32768u
#define SMEM_SZ (3 * 32768)

// ---------------- scratch ----------------
__device__ __nv_bfloat16 g_x1[(size_t)SNUM * BSZ * CD];
__device__ __nv_bfloat16 g_x2[(size_t)SNUM * BSZ * CD];
__device__ __nv_bfloat16 g_w1[(size_t)SNUM * DD * CD];
__device__ __nv_bfloat16 g_w2[(size_t)SNUM * DD * CD];
__device__ __nv_bfloat16 g_t1[(size_t)KS * M2 * DD];
__device__ __nv_bfloat16 g_t2[(size_t)KS * M2 * DD];
__device__ float  g_total[(size_t)KS * M2 * DD];
__device__ float  g_sq[KS * M2];
__device__ float  g_cs[16 * KS * DD];
__device__ float  g_inv16[KS];
__device__ double g_mmd[KS];
__device__ float  g_tprob[BSZ * 3];
__device__ double g_cls;
__device__ double g_disc;
__device__ int    g_pred;

// ---------------- helpers (compute_80-level PTX only) ----------------
__device__ __forceinline__ uint32_t smem_u32(const void* p) {
    uint32_t a;
    asm("{ .reg .u64 t; cvta.to.shared.u64 t, %1; cvt.u32.u64 %0, t; }" : "=r"(a) : "l"(p));
    return a;
}
__device__ __forceinline__ void cpa(uint32_t dst, const void* src) {
    asm volatile("cp.async.cg.shared.global [%0], [%1], 16;" :: "r"(dst), "l"(src) : "memory");
}
__device__ __forceinline__ void ldsm4(uint32_t* r, uint32_t a) {
    asm volatile("ldmatrix.sync.aligned.m8n8.x4.shared.b16 {%0,%1,%2,%3}, [%4];"
                 : "=r"(r[0]), "=r"(r[1]), "=r"(r[2]), "=r"(r[3]) : "r"(a));
}
__device__ __forceinline__ void mma16816(float* c, const uint32_t* a, const uint32_t* b) {
    asm volatile("mma.sync.aligned.m16n8k16.row.col.f32.bf16.bf16.f32 "
                 "{%0,%1,%2,%3}, {%4,%5,%6,%7}, {%8,%9}, {%0,%1,%2,%3};"
                 : "+f"(c[0]), "+f"(c[1]), "+f"(c[2]), "+f"(c[3])
                 : "r"(a[0]), "r"(a[1]), "r"(a[2]), "r"(a[3]), "r"(b[0]), "r"(b[1]));
}

// ---------------- zero accumulators ----------------
__global__ void k_zero() {
    int t = blockIdx.x * blockDim.x + threadIdx.x;
    if (t < KS * M2)  g_sq[t] = 0.f;
    if (t < BSZ * 3)  g_tprob[t] = 0.f;
    if (t < KS)       g_mmd[t] = 0.0;
    if (t == 0) { g_cls = 0.0; g_disc = 0.0; g_pred = 0; }
}

// ---------------- bf16 hi/lo splits ----------------
__device__ __forceinline__ void split4(float4 v, __nv_bfloat16* hi, __nv_bfloat16* lo, size_t t) {
    __nv_bfloat16 h0 = __float2bfloat16(v.x), h1 = __float2bfloat16(v.y);
    __nv_bfloat16 h2 = __float2bfloat16(v.z), h3 = __float2bfloat16(v.w);
    __nv_bfloat162 ph0; ph0.x = h0; ph0.y = h1;
    __nv_bfloat162 ph1; ph1.x = h2; ph1.y = h3;
    __nv_bfloat162 pl0, pl1;
    pl0.x = __float2bfloat16(v.x - __bfloat162float(h0));
    pl0.y = __float2bfloat16(v.y - __bfloat162float(h1));
    pl1.x = __float2bfloat16(v.z - __bfloat162float(h2));
    pl1.y = __float2bfloat16(v.w - __bfloat162float(h3));
    ((__nv_bfloat162*)hi)[2 * t]     = ph0;
    ((__nv_bfloat162*)hi)[2 * t + 1] = ph1;
    ((__nv_bfloat162*)lo)[2 * t]     = pl0;
    ((__nv_bfloat162*)lo)[2 * t + 1] = pl1;
}
__global__ void k_split_x(const float* __restrict__ x) {
    size_t t = (size_t)blockIdx.x * blockDim.x + threadIdx.x;
    split4(((const float4*)x)[t], g_x1, g_x2, t);
}
__global__ void k_split_w(const float* __restrict__ W) {
    size_t t = (size_t)blockIdx.x * blockDim.x + threadIdx.x;
    split4(((const float4*)W)[t], g_w1, g_w2, t);
}

// ---------------- shared pipeline: load one K-tile stage ----------------
// smem stage layout: [A1 8K][A2 8K][B1 8K][B2 8K]; each array: 2 k16-chunks of
// [128 rows][32B], swizzle: 16B-half ^= (row>>2)&1.  Conflict-free STS + LDSM.
__device__ __forceinline__ void ld_stage(uint32_t sb, int stg,
        const __nv_bfloat16* A1, const __nv_bfloat16* A2, int lda,
        const __nv_bfloat16* B1, const __nv_bfloat16* B2, int ldb, int kt) {
    int tid = threadIdx.x;
    int half = tid & 1, row = tid >> 1;
    uint32_t s0 = sb + (uint32_t)stg * STAGE_B;
    uint32_t roff = (uint32_t)(row * 32) + (uint32_t)(((half ^ ((row >> 2) & 1))) * 16);
    const __nv_bfloat16* ptrs[4] = {A1, A2, B1, B2};
    #pragma unroll
    for (int it = 0; it < 8; it++) {
        const int arr = it >> 1, kc = it & 1;
        int ld = (arr < 2) ? lda : ldb;
        const __nv_bfloat16* src = ptrs[arr] + (size_t)row * ld + kt + kc * 16 + half * 8;
        cpa(s0 + (uint32_t)(arr * 8192 + kc * 4096) + roff, src);
    }
    asm volatile("cp.async.commit_group;" ::: "memory");
}

// ---------------- shared pipeline: compute one K-tile (3-product bf16) -------
__device__ __forceinline__ void cmp_stage(uint32_t s0, int wm, int wn, int lane,
                                          float (*acc)[4][4]) {
    int arow = wm * 64 + (lane & 15);
    int ah = lane >> 4;
    int brow = wn * 32 + (lane & 7) + ((lane >> 4) << 3);
    int bh = (lane >> 3) & 1;
    #pragma unroll
    for (int kk = 0; kk < 2; kk++) {
        uint32_t base = s0 + (uint32_t)(kk * 4096);
        uint32_t af1[4][4], af2[4][4], bfr1[2][4], bfr2[2][4];
        #pragma unroll
        for (int mf = 0; mf < 4; mf++) {
            int r = arow + mf * 16;
            uint32_t off = (uint32_t)(r * 32 + ((ah ^ ((r >> 2) & 1)) * 16));
            ldsm4(af1[mf], base + off);
            ldsm4(af2[mf], base + 8192 + off);
        }
        #pragma unroll
        for (int np = 0; np < 2; np++) {
            int r = brow + np * 16;
            uint32_t off = (uint32_t)(r * 32 + ((bh ^ ((r >> 2) & 1)) * 16));
            ldsm4(bfr1[np], base + 16384 + off);
            ldsm4(bfr2[np], base + 24576 + off);
        }
        #pragma unroll
        for (int mf = 0; mf < 4; mf++)
            #pragma unroll
            for (int nf = 0; nf < 4; nf++) {
                const uint32_t* b1 = &bfr1[nf >> 1][(nf & 1) * 2];
                const uint32_t* b2 = &bfr2[nf >> 1][(nf & 1) * 2];
                mma16816(acc[mf][nf], af1[mf], b1);
                mma16816(acc[mf][nf], af1[mf], b2);
                mma16816(acc[mf][nf], af2[mf], b1);
            }
    }
}

__device__ __forceinline__ void gemm_run(uint32_t sb,
        const __nv_bfloat16* A1, const __nv_bfloat16* A2, int lda,
        const __nv_bfloat16* B1, const __nv_bfloat16* B2, int ldb,
        int NT, float (*acc)[4][4]) {
    int tid = threadIdx.x, lane = tid & 31, wid = tid >> 5;
    int wm = wid & 1, wn = wid >> 1;
    ld_stage(sb, 0, A1, A2, lda, B1, B2, ldb, 0);
    ld_stage(sb, 1, A1, A2, lda, B1, B2, ldb, 32);
    for (int ic = 0; ic < NT; ic++) {
        asm volatile("cp.async.wait_group 1;" ::: "memory");
        __syncthreads();
        if (ic + 2 < NT)
            ld_stage(sb, (ic + 2) % 3, A1, A2, lda, B1, B2, ldb, (ic + 2) * 32);
        else
            asm volatile("cp.async.commit_group;" ::: "memory");
        cmp_stage(sb + (uint32_t)(ic % 3) * STAGE_B, wm, wn, lane, acc);
    }
    __syncthreads();
}

// ---------------- stage-1: total = [src;tgt] @ W^T + b ----------------
__global__ __launch_bounds__(256) void k_mm1(const float* __restrict__ b_add,
                                             const int* __restrict__ subj_p) {
    extern __shared__ char smem[];
    uint32_t sb = smem_u32(smem);
    int k = blockIdx.z;
    int subj = *subj_p;
    int sk = (k < subj) ? k : k + 1;
    int i0 = blockIdx.y * 128, n0 = blockIdx.x * 128;
    int arow0 = (i0 < BSZ) ? (sk * BSZ + i0) : (subj * BSZ + (i0 - BSZ));
    const __nv_bfloat16* A1 = g_x1 + (size_t)arow0 * CD;
    const __nv_bfloat16* A2 = g_x2 + (size_t)arow0 * CD;
    const __nv_bfloat16* B1 = g_w1 + ((size_t)sk * DD + n0) * CD;
    const __nv_bfloat16* B2 = g_w2 + ((size_t)sk * DD + n0) * CD;

    float acc[4][4][4];
    #pragma unroll
    for (int a = 0; a < 4; a++)
        #pragma unroll
        for (int b = 0; b < 4; b++)
            #pragma unroll
            for (int c = 0; c < 4; c++) acc[a][b][c] = 0.f;

    gemm_run(sb, A1, A2, CD, B1, B2, CD, CD / 32, acc);

    int lane = threadIdx.x & 31, wid = threadIdx.x >> 5;
    int wm = wid & 1, wn = wid >> 1;
    int rb = i0 + wm * 64 + (lane >> 2);
    int cb = n0 + wn * 32 + 2 * (lane & 3);
    #pragma unroll
    for (int mf = 0; mf < 4; mf++) {
        #pragma unroll
        for (int rr = 0; rr < 2; rr++) {
            int row = rb + mf * 16 + rr * 8;
            float* trow = g_total + ((size_t)k * M2 + row) * DD;
            __nv_bfloat16* t1r = g_t1 + ((size_t)k * M2 + row) * DD;
            __nv_bfloat16* t2r = g_t2 + ((size_t)k * M2 + row) * DD;
            float s = 0.f;
            #pragma unroll
            for (int nf = 0; nf < 4; nf++) {
                int col = cb + nf * 8;
                float v0 = acc[mf][nf][rr * 2 + 0] + b_add[sk * DD + col];
                float v1 = acc[mf][nf][rr * 2 + 1] + b_add[sk * DD + col + 1];
                *(float2*)(trow + col) = make_float2(v0, v1);
                __nv_bfloat16 h0 = __float2bfloat16(v0);
                __nv_bfloat16 h1 = __float2bfloat16(v1);
                __nv_bfloat162 ph; ph.x = h0; ph.y = h1;
                __nv_bfloat162 pl;
                pl.x = __float2bfloat16(v0 - __bfloat162float(h0));
                pl.y = __float2bfloat16(v1 - __bfloat162float(h1));
                *(__nv_bfloat162*)(t1r + col) = ph;
                *(__nv_bfloat162*)(t2r + col) = pl;
                s += v0 * v0 + v1 * v1;
            }
            s += __shfl_xor_sync(0xffffffffu, s, 1);
            s += __shfl_xor_sync(0xffffffffu, s, 2);
            if ((lane & 3) == 0) atomicAdd(&g_sq[k * M2 + row], s);
        }
    }
}

// ---------------- column-sum partials ----------------
__global__ void k_colsum() {
    int k = blockIdx.x, part = blockIdx.y;
    int d = threadIdx.x;
    const float* T = g_total + (size_t)k * M2 * DD;
    float s = 0.f;
    int ib = part * 128;
    for (int i = ib; i < ib + 128; i++) s += T[(size_t)i * DD + d];
    g_cs[(part * KS + k) * DD + d] = s;
}

// ---------------- bandwidth ----------------
__global__ void k_bw() {
    __shared__ float red[512];
    int k = blockIdx.x, d = threadIdx.x;
    float s = 0.f;
    for (int p = 0; p < 16; p++) s += g_cs[(p * KS + k) * DD + d];
    red[d] = s * s;
    __syncthreads();
    for (int st = 256; st > 0; st >>= 1) { if (d < st) red[d] += red[d + st]; __syncthreads(); }
    float ssum = red[0];
    __syncthreads();
    float q = 0.f;
    for (int i = d; i < M2; i += 512) q += g_sq[k * M2 + i];
    red[d] = q;
    __syncthreads();
    for (int st = 256; st > 0; st >>= 1) { if (d < st) red[d] += red[d + st]; __syncthreads(); }
    if (d == 0) {
        double sqsum = (double)red[0];
        double m = (double)M2;
        double sumd2 = 2.0 * m * sqsum - 2.0 * (double)ssum;
        double bw = sumd2 / (m * m - m);
        bw = bw / 4.0;
        g_inv16[k] = (float)(1.0 / (16.0 * bw));
    }
}

// ---------------- Gram (3-product bf16 mma) + fused multi-bandwidth RBF -------
__global__ __launch_bounds__(256) void k_gram() {
    int k = blockIdx.z;
    int bi = blockIdx.y, bj = blockIdx.x;
    if (bj < bi) return;
    extern __shared__ char smem[];
    uint32_t sb = smem_u32(smem);
    int i0 = bi * 128, j0 = bj * 128;
    const __nv_bfloat16* A1 = g_t1 + ((size_t)k * M2 + i0) * DD;
    const __nv_bfloat16* A2 = g_t2 + ((size_t)k * M2 + i0) * DD;
    const __nv_bfloat16* B1 = g_t1 + ((size_t)k * M2 + j0) * DD;
    const __nv_bfloat16* B2 = g_t2 + ((size_t)k * M2 + j0) * DD;

    float acc[4][4][4];
    #pragma unroll
    for (int a = 0; a < 4; a++)
        #pragma unroll
        for (int b = 0; b < 4; b++)
            #pragma unroll
            for (int c = 0; c < 4; c++) acc[a][b][c] = 0.f;

    gemm_run(sb, A1, A2, DD, B1, B2, DD, DD / 32, acc);

    int lane = threadIdx.x & 31, wid = threadIdx.x >> 5;
    int wm = wid & 1, wn = wid >> 1;
    int ib = i0 + wm * 64 + (lane >> 2);
    int jb = j0 + wn * 32 + 2 * (lane & 3);
    float inv = g_inv16[k];
    float sqj[8];
    #pragma unroll
    for (int nf = 0; nf < 4; nf++) {
        sqj[nf * 2 + 0] = g_sq[k * M2 + jb + nf * 8 + 0];
        sqj[nf * 2 + 1] = g_sq[k * M2 + jb + nf * 8 + 1];
    }
    float av = 0.f;
    #pragma unroll
    for (int mf = 0; mf < 4; mf++) {
        #pragma unroll
        for (int rr = 0; rr < 2; rr++) {
            int i = ib + mf * 16 + rr * 8;
            float sqi = g_sq[k * M2 + i];
            bool hi = (i < BSZ);
            #pragma unroll
            for (int nf = 0; nf < 4; nf++) {
                #pragma unroll
                for (int e = 0; e < 2; e++) {
                    int j = jb + nf * 8 + e;
                    float d2 = sqi + sqj[nf * 2 + e] - 2.f * acc[mf][nf][rr * 2 + e];
                    float ex = __expf(-d2 * inv);
                    float s5 = ex;
                    ex *= ex; s5 += ex;
                    ex *= ex; s5 += ex;
                    ex *= ex; s5 += ex;
                    ex *= ex; s5 += ex;
                    float w = (j > i) ? 2.f : ((j == i) ? 1.f : 0.f);
                    float sg = (hi == (j < BSZ)) ? 1.f : -1.f;
                    av += sg * w * s5;
                }
            }
        }
    }
    #pragma unroll
    for (int o = 16; o; o >>= 1) av += __shfl_xor_sync(0xffffffffu, av, o);
    float* red = (float*)smem;    // pipeline buffers dead after gemm_run's sync
    if (lane == 0) red[wid] = av;
    __syncthreads();
    if (threadIdx.x == 0) {
        float s = 0.f;
        #pragma unroll
        for (int wq = 0; wq < 8; wq++) s += red[wq];
        atomicAdd(&g_mmd[k], (double)s);
    }
}

// ---------------- classifier head ----------------
__global__ void k_cls(const float* __restrict__ y, const float* __restrict__ W_cls,
                      const float* __restrict__ b_cls, const int* __restrict__ subj_p) {
    int gw = (blockIdx.x * blockDim.x + threadIdx.x) >> 5;
    int lane = threadIdx.x & 31;
    if (gw >= KS * M2) return;
    int k = gw / M2;
    int r = gw % M2;
    const float* row = g_total + (size_t)gw * DD;
    const float* Wc = W_cls + (size_t)k * 3 * DD;
    float a0 = 0.f, a1 = 0.f, a2 = 0.f;
    for (int d = lane; d < DD; d += 32) {
        float v = fmaxf(row[d], 0.f);
        a0 += v * Wc[d];
        a1 += v * Wc[DD + d];
        a2 += v * Wc[2 * DD + d];
    }
    #pragma unroll
    for (int o = 16; o; o >>= 1) {
        a0 += __shfl_xor_sync(0xffffffffu, a0, o);
        a1 += __shfl_xor_sync(0xffffffffu, a1, o);
        a2 += __shfl_xor_sync(0xffffffffu, a2, o);
    }
    if (lane == 0) {
        int subj = *subj_p;
        float l0 = a0 + b_cls[k * 3 + 0];
        float l1 = a1 + b_cls[k * 3 + 1];
        float l2 = a2 + b_cls[k * 3 + 2];
        float m = fmaxf(l0, fmaxf(l1, l2));
        float e0 = expf(l0 - m), e1 = expf(l1 - m), e2 = expf(l2 - m);
        float sum = e0 + e1 + e2;
        if (r < BSZ) {
            int sk = (k < subj) ? k : k + 1;
            const float* yr = y + (size_t)(sk * BSZ + r) * 3;
            int lab = (yr[1] > yr[0]) ? ((yr[2] > yr[1]) ? 2 : 1) : ((yr[2] > yr[0]) ? 2 : 0);
            float li = (lab == 0) ? l0 : ((lab == 1) ? l1 : l2);
            atomicAdd(&g_cls, (double)(m + logf(sum) - li));
        } else {
            int b = r - BSZ;
            float invs = 1.f / sum;
            atomicAdd(&g_tprob[b * 3 + 0], e0 * invs);
            atomicAdd(&g_tprob[b * 3 + 1], e1 * invs);
            atomicAdd(&g_tprob[b * 3 + 2], e2 * invs);
        }
    }
}

// ---------------- prediction count ----------------
__global__ void k_pred(const float* __restrict__ y, const int* __restrict__ subj_p) {
    int b = blockIdx.x * blockDim.x + threadIdx.x;
    if (b >= BSZ) return;
    int subj = *subj_p;
    float p0 = g_tprob[b * 3], p1 = g_tprob[b * 3 + 1], p2 = g_tprob[b * 3 + 2];
    int am = (p1 > p0) ? ((p2 > p1) ? 2 : 1) : ((p2 > p0) ? 2 : 0);
    const float* yr = y + (size_t)(subj * BSZ + b) * 3;
    int lab = (yr[1] > yr[0]) ? ((yr[2] > yr[1]) ? 2 : 1) : ((yr[2] > yr[0]) ? 2 : 0);
    if (am == lab) atomicAdd(&g_pred, 1);
}

// ---------------- pairwise softmax discrepancy ----------------
__global__ void k_disc() {
    __shared__ float P[KS][513];
    int b = blockIdx.x;
    int w = threadIdx.x >> 5, lane = threadIdx.x & 31;
    for (int k = w; k < KS; k += 8) {
        const float* row = g_total + ((size_t)k * M2 + b) * DD;
        float m = -1e30f;
        for (int d = lane; d < DD; d += 32) m = fmaxf(m, row[d]);
        #pragma unroll
        for (int o = 16; o; o >>= 1) m = fmaxf(m, __shfl_xor_sync(0xffffffffu, m, o));
        float ssum = 0.f;
        for (int d = lane; d < DD; d += 32) {
            float e = __expf(row[d] - m);
            P[k][d] = e;
            ssum += e;
        }
        #pragma unroll
        for (int o = 16; o; o >>= 1) ssum += __shfl_xor_sync(0xffffffffu, ssum, o);
        float invs = 1.f / ssum;
        for (int d = lane; d < DD; d += 32) P[k][d] *= invs;
    }
    __syncthreads();
    float acc = 0.f;
    for (int d = threadIdx.x; d < DD; d += 256) {
        float p[KS];
        #pragma unroll
        for (int k = 0; k < KS; k++) p[k] = P[k][d];
        #pragma unroll
        for (int i = 0; i < KS; i++)
            #pragma unroll
            for (int j = i + 1; j < KS; j++)
                acc += fabsf(p[i] - p[j]);
    }
    #pragma unroll
    for (int o = 16; o; o >>= 1) acc += __shfl_xor_sync(0xffffffffu, acc, o);
    __shared__ float ws[8];
    if ((threadIdx.x & 31) == 0) ws[threadIdx.x >> 5] = acc;
    __syncthreads();
    if (threadIdx.x == 0) {
        float s = 0.f;
        #pragma unroll
        for (int i = 0; i < 8; i++) s += ws[i];
        atomicAdd(&g_disc, (double)s);
    }
}

// ---------------- finalize ----------------
__global__ void k_fin(float* __restrict__ out) {
    if (threadIdx.x == 0 && blockIdx.x == 0) {
        double mmd = 0.0;
        for (int k = 0; k < KS; k++) mmd += g_mmd[k];
        mmd /= (double)KS * (double)BSZ * (double)BSZ;
        out[0] = (float)(0.1 * mmd);
        double disc = g_disc / ((double)BSZ * (double)DD) * 2.0 / ((double)KS * (KS - 1));
        out[1] = (float)(0.4 * disc);
        out[2] = (float)(g_cls / ((double)KS * (double)BSZ));
        out[3] = (float)g_pred;
        out[4] = (float)BSZ;
    }
}

// ---------------- launch ----------------
extern "C" void kernel_launch(void* const* d_in, const int* in_sizes, int n_in,
                              void* d_out, int out_size) {
    const float* x     = (const float*)d_in[0];
    const float* y     = (const float*)d_in[1];
    const float* W_add = (const float*)d_in[3];
    const float* b_add = (const float*)d_in[4];
    const float* W_cls = (const float*)d_in[5];
    const float* b_cls = (const float*)d_in[6];
    const int*   subj  = (const int*)d_in[7];

    cudaFuncSetAttribute(k_mm1,  cudaFuncAttributeMaxDynamicSharedMemorySize, SMEM_SZ);
    cudaFuncSetAttribute(k_gram, cudaFuncAttributeMaxDynamicSharedMemorySize, SMEM_SZ);

    k_zero<<<112, 256>>>();
    k_split_x<<<(SNUM * BSZ * CD / 4) / 256, 256>>>(x);
    k_split_w<<<(SNUM * DD * CD / 4) / 256, 256>>>(W_add);
    k_mm1<<<dim3(4, 16, KS), 256, SMEM_SZ>>>(b_add, subj);
    k_colsum<<<dim3(KS, 16), 512>>>();
    k_bw<<<KS, 512>>>();
    k_gram<<<dim3(16, 16, KS), 256, SMEM_SZ>>>();
    k_cls<<<(KS * M2) / 8, 256>>>(y, W_cls, b_cls, subj);
    k_pred<<<4, 256>>>(y, subj);
    k_disc<<<BSZ, 256>>>();
    k_fin<<<1, 32>>>((float*)d_out);
}